// round 12
// baseline (speedup 1.0000x reference)
#include <cuda_runtime.h>
#include <cuda_bf16.h>
#include <cstdint>

// ---------------------------------------------------------------------------
// INT8Linear on sm_103 (no tcgen05 at this ptxas target; legacy int8 IMMA is
// de-rated). Exact int8 GEMM emulated with bf16 mma.sync.m16n8k16 (int8 exact
// in bf16; K=1024 integer partial sums < 2^24 -> exact fp32 accumulation):
//   out[m][n] = (sum_k Xq[m][k]*Wq[n][k]) * xs[m] * ws[n] + bias[n]
// GEMM: 256x128 tile, BK=64, 512 threads (16 warps, 4Mx4N), 4-stage cp.async
// pipeline, XOR-swizzled SMEM, wait_group 2, one __syncthreads per K-iter.
// ---------------------------------------------------------------------------

static constexpr int DIN   = 1024;
static constexpr int DOUT  = 1024;
static constexpr int MAX_M = 32768;

__device__ __nv_bfloat16 g_Xq[(size_t)MAX_M * DIN];   // 64 MB row-major [M][K]
__device__ __nv_bfloat16 g_Wq[(size_t)DOUT  * DIN];   //  2 MB row-major [N][K]
__device__ float         g_xs[MAX_M];
__device__ float         g_ws[DOUT];

// ============================ Quantizers ===================================
__device__ __forceinline__ void quant_row_warp(const float* __restrict__ src,
                                               __nv_bfloat16* __restrict__ dq,
                                               float* __restrict__ ds,
                                               int row, int lane) {
    float4 v[8];
    const float4* s4 = reinterpret_cast<const float4*>(src + (size_t)row * 1024);
    #pragma unroll
    for (int j = 0; j < 8; j++) v[j] = s4[lane + 32 * j];

    float am = 0.0f;
    #pragma unroll
    for (int j = 0; j < 8; j++)
        am = fmaxf(am, fmaxf(fmaxf(fabsf(v[j].x), fabsf(v[j].y)),
                             fmaxf(fabsf(v[j].z), fabsf(v[j].w))));
    #pragma unroll
    for (int o = 16; o > 0; o >>= 1)
        am = fmaxf(am, __shfl_xor_sync(0xffffffffu, am, o));

    const float amax  = fmaxf(am, 1e-8f);
    const float scale = amax / 127.0f;
    if (lane == 0) ds[row] = scale;

    uint2* drow = reinterpret_cast<uint2*>(dq + (size_t)row * 1024);
    #pragma unroll
    for (int j = 0; j < 8; j++) {
        float q0 = fminf(fmaxf(rintf(v[j].x / scale), -128.0f), 127.0f);
        float q1 = fminf(fmaxf(rintf(v[j].y / scale), -128.0f), 127.0f);
        float q2 = fminf(fmaxf(rintf(v[j].z / scale), -128.0f), 127.0f);
        float q3 = fminf(fmaxf(rintf(v[j].w / scale), -128.0f), 127.0f);
        __nv_bfloat162 p0 = __floats2bfloat162_rn(q0, q1);
        __nv_bfloat162 p1 = __floats2bfloat162_rn(q2, q3);
        uint2 pk;
        pk.x = *reinterpret_cast<uint32_t*>(&p0);
        pk.y = *reinterpret_cast<uint32_t*>(&p1);
        drow[lane + 32 * j] = pk;
    }
}

__global__ __launch_bounds__(256) void quant_x_kernel(const float* __restrict__ x) {
    quant_row_warp(x, g_Xq, g_xs, blockIdx.x * 8 + (threadIdx.x >> 5), threadIdx.x & 31);
}
__global__ __launch_bounds__(256) void quant_w_kernel(const float* __restrict__ w) {
    quant_row_warp(w, g_Wq, g_ws, blockIdx.x * 8 + (threadIdx.x >> 5), threadIdx.x & 31);
}

// ============================ GEMM (bf16 HMMA) =============================
#define BM 256
#define BN 128
#define BK 64
#define STAGES 4
#define NTHREADS 512
// Swizzled rows: 128B/row, byte col c -> c ^ ((r & 7) * 16). No padding.
static constexpr uint32_t STAGE_A_BYTES = BM * 128;              // 32768
static constexpr uint32_t STAGE_B_BYTES = BN * 128;              // 16384
static constexpr uint32_t STAGE_BYTES   = STAGE_A_BYTES + STAGE_B_BYTES; // 49152
static constexpr uint32_t GEMM_SMEM     = STAGES * STAGE_BYTES;  // 196608

#define CP_ASYNC16(dst, src) \
    asm volatile("cp.async.cg.shared.global [%0], [%1], 16;" :: "r"(dst), "l"(src))
#define CP_COMMIT() asm volatile("cp.async.commit_group;" ::: "memory")
#define CP_WAIT2()  asm volatile("cp.async.wait_group 2;" ::: "memory")

__device__ __forceinline__ void load_stage(uint32_t s_base,
                                           const __nv_bfloat16* a_g,
                                           const __nv_bfloat16* b_g,
                                           int k0, int tid) {
    // A: 256 rows x 8 chunks of 16B (2048 chunks); B: 128 rows (1024 chunks).
    #pragma unroll
    for (int i = 0; i < 4; i++) {
        const int v = tid + NTHREADS * i;
        const int r = v >> 3;
        const int c = (v & 7) * 16;
        const uint32_t sc = (uint32_t)(c ^ ((r & 7) * 16));
        CP_ASYNC16(s_base + r * 128 + sc,
                   (const char*)(a_g + (size_t)r * DIN + k0) + c);
    }
    #pragma unroll
    for (int i = 0; i < 2; i++) {
        const int v = tid + NTHREADS * i;
        const int r = v >> 3;
        const int c = (v & 7) * 16;
        const uint32_t sc = (uint32_t)(c ^ ((r & 7) * 16));
        CP_ASYNC16(s_base + STAGE_A_BYTES + r * 128 + sc,
                   (const char*)(b_g + (size_t)r * DIN + k0) + c);
    }
}

__global__ __launch_bounds__(NTHREADS, 1)
void gemm_hmma_kernel(const float* __restrict__ bias, float* __restrict__ out) {
    extern __shared__ __align__(16) unsigned char smem[];
    const uint32_t sb = (uint32_t)__cvta_generic_to_shared(smem);

    const int tid  = threadIdx.x;
    const int warp = tid >> 5;
    const int lane = tid & 31;
    const int bm   = blockIdx.y * BM;
    const int bn   = blockIdx.x * BN;
    const int wm   = (warp & 3) * 64;    // 4 M-warps cover 256
    const int wn   = (warp >> 2) * 32;   // 4 N-warps cover 128

    const __nv_bfloat16* a_g = g_Xq + (size_t)bm * DIN;
    const __nv_bfloat16* b_g = g_Wq + (size_t)bn * DIN;

    float acc[4][4][4];
    #pragma unroll
    for (int im = 0; im < 4; im++)
        #pragma unroll
        for (int n = 0; n < 4; n++)
            #pragma unroll
            for (int r = 0; r < 4; r++) acc[im][n][r] = 0.0f;

    // Prologue: stages 0..2
    #pragma unroll
    for (int p = 0; p < STAGES - 1; p++) {
        load_stage(sb + p * STAGE_BYTES, a_g, b_g, p * BK, tid);
        CP_COMMIT();
    }

    const int NKT = DIN / BK;  // 16
    #pragma unroll 1
    for (int kt = 0; kt < NKT; kt++) {
        CP_WAIT2();              // stage kt complete (two newer may pend)
        __syncthreads();         // all warps done reading stage (kt+3)%4

        const int kp = kt + STAGES - 1;   // prefetch stage kt+3
        if (kp < NKT)
            load_stage(sb + (kp % STAGES) * STAGE_BYTES, a_g, b_g, kp * BK, tid);
        CP_COMMIT();             // uniform commits keep wait_group semantics

        const uint32_t sa = sb + (kt % STAGES) * STAGE_BYTES;
        const uint32_t sB = sa + STAGE_A_BYTES;

        #pragma unroll
        for (int ks = 0; ks < 4; ks++) {
            const int kb = ks * 32;          // byte col of 16-elem K group
            uint32_t a[4][4], b[4][2];

            #pragma unroll
            for (int im = 0; im < 4; im++) {
                const int r = wm + im * 16 + (lane & 15);
                const int c = kb + (lane >> 4) * 16;
                asm volatile(
                    "ldmatrix.sync.aligned.m8n8.x4.shared.b16 {%0,%1,%2,%3}, [%4];"
                    : "=r"(a[im][0]), "=r"(a[im][1]), "=r"(a[im][2]), "=r"(a[im][3])
                    : "r"(sa + r * 128 + (uint32_t)(c ^ ((r & 7) * 16))));
            }
            #pragma unroll
            for (int np = 0; np < 2; np++) {
                const int g   = lane >> 3;
                const int col = wn + np * 16 + (g >> 1) * 8 + (lane & 7);
                const int c   = kb + (g & 1) * 16;
                asm volatile(
                    "ldmatrix.sync.aligned.m8n8.x4.shared.b16 {%0,%1,%2,%3}, [%4];"
                    : "=r"(b[2 * np][0]), "=r"(b[2 * np][1]),
                      "=r"(b[2 * np + 1][0]), "=r"(b[2 * np + 1][1])
                    : "r"(sB + col * 128 + (uint32_t)(c ^ ((col & 7) * 16))));
            }
            #pragma unroll
            for (int im = 0; im < 4; im++) {
                #pragma unroll
                for (int n = 0; n < 4; n++) {
                    asm volatile(
                        "mma.sync.aligned.m16n8k16.row.col.f32.bf16.bf16.f32 "
                        "{%0,%1,%2,%3}, {%4,%5,%6,%7}, {%8,%9}, {%0,%1,%2,%3};"
                        : "+f"(acc[im][n][0]), "+f"(acc[im][n][1]),
                          "+f"(acc[im][n][2]), "+f"(acc[im][n][3])
                        : "r"(a[im][0]), "r"(a[im][1]), "r"(a[im][2]), "r"(a[im][3]),
                          "r"(b[n][0]), "r"(b[n][1]));
                }
            }
        }
        // no bottom barrier: next iteration's top barrier is the fence
    }

    // Epilogue: dequant + bias.
    #pragma unroll
    for (int im = 0; im < 4; im++) {
        const int row0 = bm + wm + im * 16 + (lane >> 2);
        const float xs0 = g_xs[row0];
        const float xs8 = g_xs[row0 + 8];
        #pragma unroll
        for (int n = 0; n < 4; n++) {
            const int col = bn + wn + n * 8 + (lane & 3) * 2;
            const float ws0 = g_ws[col],  ws1 = g_ws[col + 1];
            const float bb0 = bias[col],  bb1 = bias[col + 1];
            float2 o0, o1;
            o0.x = acc[im][n][0] * xs0 * ws0 + bb0;
            o0.y = acc[im][n][1] * xs0 * ws1 + bb1;
            o1.x = acc[im][n][2] * xs8 * ws0 + bb0;
            o1.y = acc[im][n][3] * xs8 * ws1 + bb1;
            *reinterpret_cast<float2*>(out + (size_t)row0 * DOUT + col)       = o0;
            *reinterpret_cast<float2*>(out + (size_t)(row0 + 8) * DOUT + col) = o1;
        }
    }
}

// ---------------------------------------------------------------------------
extern "C" void kernel_launch(void* const* d_in, const int* in_sizes, int n_in,
                              void* d_out, int out_size) {
    const float* x    = (const float*)d_in[0];
    const float* w    = (const float*)d_in[1];
    const float* bias = (const float*)d_in[2];
    float* out        = (float*)d_out;

    const int M = in_sizes[0] / DIN;  // 32768

    quant_w_kernel<<<DOUT / 8, 256>>>(w);
    quant_x_kernel<<<M / 8, 256>>>(x);

    cudaFuncSetAttribute(gemm_hmma_kernel,
                         cudaFuncAttributeMaxDynamicSharedMemorySize, GEMM_SMEM);
    dim3 grid(DOUT / BN, M / BM);  // (8, 128)
    gemm_hmma_kernel<<<grid, NTHREADS, GEMM_SMEM>>>(bias, out);
}

// round 16
// speedup vs baseline: 1.0504x; 1.0504x over previous
#include <cuda_runtime.h>
#include <cuda_bf16.h>
#include <cstdint>

// ---------------------------------------------------------------------------
// INT8Linear on sm_103 (no tcgen05 at this ptxas target; legacy int8 IMMA is
// de-rated). Exact int8 GEMM emulated with bf16 mma.sync.m16n8k16 (int8 exact
// in bf16; K=1024 integer partial sums < 2^24 -> exact fp32 accumulation):
//   out[m][n] = (sum_k Xq[m][k]*Wq[n][k]) * xs[m] * ws[n] + bias[n]
// R8 GEMM (128x128, BK=64, 3-stage cp.async, swizzled, 2 CTA/SM) with
// quant_x FUSED as a cooperative prologue: the 8 CTAs sharing an M-block
// each quantize 16 rows, publish flags, and spin-wait before loading.
// ---------------------------------------------------------------------------

static constexpr int DIN   = 1024;
static constexpr int DOUT  = 1024;
static constexpr int MAX_M = 32768;
static constexpr int MBLK  = MAX_M / 128;   // 256 M-blocks

__device__ __nv_bfloat16 g_Xq[(size_t)MAX_M * DIN];   // 64 MB row-major [M][K]
__device__ __nv_bfloat16 g_Wq[(size_t)DOUT  * DIN];   //  2 MB row-major [N][K]
__device__ float         g_xs[MAX_M];
__device__ float         g_ws[DOUT];
__device__ int           g_flags[MBLK * 8];           // per-(bm,bn) quant-done

// ============================ sync helpers =================================
__device__ __forceinline__ int ld_acquire(const int* p) {
    int v;
    asm volatile("ld.acquire.gpu.global.b32 %0, [%1];" : "=r"(v) : "l"(p) : "memory");
    return v;
}
__device__ __forceinline__ void st_release(int* p, int v) {
    asm volatile("st.release.gpu.global.b32 [%0], %1;" :: "l"(p), "r"(v) : "memory");
}

// ============================ Quantizer ====================================
// One warp quantizes one row of 1024 floats. scale = max(amax,1e-8)/127,
// q = clip(rint(v/scale),-128,127) stored as bf16 (exact).
__device__ __forceinline__ void quant_row_warp(const float* __restrict__ src,
                                               __nv_bfloat16* __restrict__ dq,
                                               float* __restrict__ ds,
                                               int row, int lane) {
    float4 v[8];
    const float4* s4 = reinterpret_cast<const float4*>(src + (size_t)row * 1024);
    #pragma unroll
    for (int j = 0; j < 8; j++) v[j] = s4[lane + 32 * j];

    float am = 0.0f;
    #pragma unroll
    for (int j = 0; j < 8; j++)
        am = fmaxf(am, fmaxf(fmaxf(fabsf(v[j].x), fabsf(v[j].y)),
                             fmaxf(fabsf(v[j].z), fabsf(v[j].w))));
    #pragma unroll
    for (int o = 16; o > 0; o >>= 1)
        am = fmaxf(am, __shfl_xor_sync(0xffffffffu, am, o));

    const float amax  = fmaxf(am, 1e-8f);
    const float scale = amax / 127.0f;
    if (lane == 0) ds[row] = scale;

    uint2* drow = reinterpret_cast<uint2*>(dq + (size_t)row * 1024);
    #pragma unroll
    for (int j = 0; j < 8; j++) {
        float q0 = fminf(fmaxf(rintf(v[j].x / scale), -128.0f), 127.0f);
        float q1 = fminf(fmaxf(rintf(v[j].y / scale), -128.0f), 127.0f);
        float q2 = fminf(fmaxf(rintf(v[j].z / scale), -128.0f), 127.0f);
        float q3 = fminf(fmaxf(rintf(v[j].w / scale), -128.0f), 127.0f);
        __nv_bfloat162 p0 = __floats2bfloat162_rn(q0, q1);
        __nv_bfloat162 p1 = __floats2bfloat162_rn(q2, q3);
        uint2 pk;
        pk.x = *reinterpret_cast<uint32_t*>(&p0);
        pk.y = *reinterpret_cast<uint32_t*>(&p1);
        drow[lane + 32 * j] = pk;
    }
}

// quant_w + flag reset (runs before the fused kernel each launch)
__global__ __launch_bounds__(256) void quant_w_kernel(const float* __restrict__ w) {
    quant_row_warp(w, g_Wq, g_ws, blockIdx.x * 8 + (threadIdx.x >> 5), threadIdx.x & 31);
    if (blockIdx.x == 0) {
        #pragma unroll
        for (int i = 0; i < MBLK * 8 / 256; i++)
            g_flags[threadIdx.x + 256 * i] = 0;
    }
}

// ============================ Fused quant_x + GEMM =========================
#define BM 128
#define BN 128
#define BK 64
#define STAGES 3
// Swizzled rows: 128B/row, byte col c -> c ^ ((r & 7) * 16). No padding.
static constexpr uint32_t STAGE_A_BYTES = BM * 128;              // 16384
static constexpr uint32_t STAGE_BYTES   = 2 * STAGE_A_BYTES;     // 32768
static constexpr uint32_t GEMM_SMEM     = STAGES * STAGE_BYTES;  // 98304

#define CP_ASYNC16(dst, src) \
    asm volatile("cp.async.cg.shared.global [%0], [%1], 16;" :: "r"(dst), "l"(src))
#define CP_COMMIT() asm volatile("cp.async.commit_group;" ::: "memory")
#define CP_WAIT1()  asm volatile("cp.async.wait_group 1;" ::: "memory")

__device__ __forceinline__ void load_stage(uint32_t s_base,
                                           const __nv_bfloat16* a_g,
                                           const __nv_bfloat16* b_g,
                                           int k0, int tid) {
    #pragma unroll
    for (int i = 0; i < 4; i++) {
        const int v = tid + 256 * i;
        const int r = v >> 3;
        const int c = (v & 7) * 16;
        const uint32_t sc = (uint32_t)(c ^ ((r & 7) * 16));
        CP_ASYNC16(s_base + r * 128 + sc,
                   (const char*)(a_g + (size_t)r * DIN + k0) + c);
        CP_ASYNC16(s_base + STAGE_A_BYTES + r * 128 + sc,
                   (const char*)(b_g + (size_t)r * DIN + k0) + c);
    }
}

__global__ __launch_bounds__(256, 2)
void gemm_fused_kernel(const float* __restrict__ x,
                       const float* __restrict__ bias,
                       float* __restrict__ out) {
    extern __shared__ __align__(16) unsigned char smem[];
    const uint32_t sb = (uint32_t)__cvta_generic_to_shared(smem);

    const int tid  = threadIdx.x;
    const int warp = tid >> 5;
    const int lane = tid & 31;
    const int bnb  = blockIdx.x;          // 0..7
    const int bmb  = blockIdx.y;          // 0..255
    const int bm   = bmb * BM;
    const int bn   = bnb * BN;
    const int wm   = (warp & 1) * 64;
    const int wn   = (warp >> 1) * 32;

    // ---- cooperative quant of this M-block: this CTA does 16 rows ----
    {
        const int qbase = bm + bnb * 16;          // 16 rows for this CTA
        quant_row_warp(x, g_Xq, g_xs, qbase + 2 * warp,     lane);
        quant_row_warp(x, g_Xq, g_xs, qbase + 2 * warp + 1, lane);
        __threadfence();
        __syncthreads();
        if (tid == 0) st_release(&g_flags[bmb * 8 + bnb], 1);
        // wait for all 8 slices of this M-block
        if (tid < 8) {
            const int* f = &g_flags[bmb * 8 + tid];
            while (ld_acquire(f) == 0) __nanosleep(64);
        }
        __syncthreads();
    }

    const __nv_bfloat16* a_g = g_Xq + (size_t)bm * DIN;
    const __nv_bfloat16* b_g = g_Wq + (size_t)bn * DIN;

    float acc[4][4][4];
    #pragma unroll
    for (int im = 0; im < 4; im++)
        #pragma unroll
        for (int n = 0; n < 4; n++)
            #pragma unroll
            for (int r = 0; r < 4; r++) acc[im][n][r] = 0.0f;

    // Prologue: stages 0, 1
    load_stage(sb + 0 * STAGE_BYTES, a_g, b_g, 0 * BK, tid);
    CP_COMMIT();
    load_stage(sb + 1 * STAGE_BYTES, a_g, b_g, 1 * BK, tid);
    CP_COMMIT();

    const int NKT = DIN / BK;  // 16
    #pragma unroll 1
    for (int kt = 0; kt < NKT; kt++) {
        CP_WAIT1();              // stage kt complete (one newer may pend)
        __syncthreads();         // all warps done reading stage (kt+2)%3

        const int kp = kt + 2;
        if (kp < NKT)
            load_stage(sb + (kp % STAGES) * STAGE_BYTES, a_g, b_g, kp * BK, tid);
        CP_COMMIT();

        const uint32_t sa = sb + (kt % STAGES) * STAGE_BYTES;
        const uint32_t sB = sa + STAGE_A_BYTES;

        #pragma unroll
        for (int ks = 0; ks < 4; ks++) {
            const int kb = ks * 32;
            uint32_t a[4][4], b[4][2];

            #pragma unroll
            for (int im = 0; im < 4; im++) {
                const int r = wm + im * 16 + (lane & 15);
                const int c = kb + (lane >> 4) * 16;
                asm volatile(
                    "ldmatrix.sync.aligned.m8n8.x4.shared.b16 {%0,%1,%2,%3}, [%4];"
                    : "=r"(a[im][0]), "=r"(a[im][1]), "=r"(a[im][2]), "=r"(a[im][3])
                    : "r"(sa + r * 128 + (uint32_t)(c ^ ((r & 7) * 16))));
            }
            #pragma unroll
            for (int np = 0; np < 2; np++) {
                const int g   = lane >> 3;
                const int col = wn + np * 16 + (g >> 1) * 8 + (lane & 7);
                const int c   = kb + (g & 1) * 16;
                asm volatile(
                    "ldmatrix.sync.aligned.m8n8.x4.shared.b16 {%0,%1,%2,%3}, [%4];"
                    : "=r"(b[2 * np][0]), "=r"(b[2 * np][1]),
                      "=r"(b[2 * np + 1][0]), "=r"(b[2 * np + 1][1])
                    : "r"(sB + col * 128 + (uint32_t)(c ^ ((col & 7) * 16))));
            }
            #pragma unroll
            for (int im = 0; im < 4; im++) {
                #pragma unroll
                for (int n = 0; n < 4; n++) {
                    asm volatile(
                        "mma.sync.aligned.m16n8k16.row.col.f32.bf16.bf16.f32 "
                        "{%0,%1,%2,%3}, {%4,%5,%6,%7}, {%8,%9}, {%0,%1,%2,%3};"
                        : "+f"(acc[im][n][0]), "+f"(acc[im][n][1]),
                          "+f"(acc[im][n][2]), "+f"(acc[im][n][3])
                        : "r"(a[im][0]), "r"(a[im][1]), "r"(a[im][2]), "r"(a[im][3]),
                          "r"(b[n][0]), "r"(b[n][1]));
                }
            }
        }
    }

    // Epilogue: dequant + bias.
    #pragma unroll
    for (int im = 0; im < 4; im++) {
        const int row0 = bm + wm + im * 16 + (lane >> 2);
        const float xs0 = g_xs[row0];
        const float xs8 = g_xs[row0 + 8];
        #pragma unroll
        for (int n = 0; n < 4; n++) {
            const int col = bn + wn + n * 8 + (lane & 3) * 2;
            const float ws0 = g_ws[col],  ws1 = g_ws[col + 1];
            const float bb0 = bias[col],  bb1 = bias[col + 1];
            float2 o0, o1;
            o0.x = acc[im][n][0] * xs0 * ws0 + bb0;
            o0.y = acc[im][n][1] * xs0 * ws1 + bb1;
            o1.x = acc[im][n][2] * xs8 * ws0 + bb0;
            o1.y = acc[im][n][3] * xs8 * ws1 + bb1;
            *reinterpret_cast<float2*>(out + (size_t)row0 * DOUT + col)       = o0;
            *reinterpret_cast<float2*>(out + (size_t)(row0 + 8) * DOUT + col) = o1;
        }
    }
}

// ---------------------------------------------------------------------------
extern "C" void kernel_launch(void* const* d_in, const int* in_sizes, int n_in,
                              void* d_out, int out_size) {
    const float* x    = (const float*)d_in[0];
    const float* w    = (const float*)d_in[1];
    const float* bias = (const float*)d_in[2];
    float* out        = (float*)d_out;

    quant_w_kernel<<<DOUT / 8, 256>>>(w);   // also resets g_flags

    cudaFuncSetAttribute(gemm_fused_kernel,
                         cudaFuncAttributeMaxDynamicSharedMemorySize, GEMM_SMEM);
    dim3 grid(DOUT / BN, MAX_M / BM);  // (8, 256)
    gemm_fused_kernel<<<grid, 256, GEMM_SMEM>>>(x, bias, out);
}